// round 12
// baseline (speedup 1.0000x reference)
#include <cuda_runtime.h>
#include <cuda_bf16.h>
#include <math.h>

// GAT layer, fully collapsed:
//   s1 = h @ (W a1), s2 = h @ (W a2)
//   m_i = leaky(s1_i + max_j s2_j)
//   Z_i = e^{s1_i-m_i} * SUM_{s2_j > -s1_i} e^{s2_j} + e^{.2 s1_i-m_i} * SUM_{s2_j <= -s1_i} e^{.2 s2_j}
//   c_j = e^{s2_j} * SUM_{s1_i > -s2_j} g1_i + e^{.2 s2_j} * SUM_{s1_i <= -s2_j} g2_i
//   out[b] = (1/N) * (c^T h) @ W
// Threshold sums via 1024-bin bucket structures. Both structures' skeletons
// (histogram, offsets, key scatter) are built concurrently sharing barriers;
// elements are packed float4 (key, pA, pB, -) so boundary loops are LDS.128.
// Branch selection is exact fp compare.

#define B 8
#define N 2048
#define FIN 128
#define FOUT 64
#define ALPHA 0.2f
#define NB 1024

// dynamic smem: pk2[N] float4, pk1[N] float4, binA[NB], binB[NB],
//               cnt2[NB] int, cnt1[NB] int, off2[NB+1] int, off1[NB+1] int
#define SMEM_ATTN (2 * N * 16 + 2 * NB * 4 + 2 * NB * 4 + 2 * (NB + 1) * 4)

__device__ float d_u1[FIN];
__device__ float d_u2[FIN];
__device__ float d_s1[B * N];
__device__ float d_s2[B * N];
__device__ float d_c[B * N];
__device__ float d_v[B * FIN];

__device__ __forceinline__ float leaky(float x) { return x >= 0.f ? x : ALPHA * x; }

__device__ __forceinline__ int binOf(float x, float lo, float scale) {
    float f = (x - lo) * scale;
    f = fminf(fmaxf(f, 0.f), (float)(NB - 1));
    return (int)f;
}

// ---------------- K1: u1 = W a1, u2 = W a2; zero d_v ----------------
__global__ void k_prep(const float* __restrict__ W, const float* __restrict__ a) {
    int t = threadIdx.x;            // 1024 threads
    d_v[t] = 0.f;                   // B*FIN = 1024
    if (t < FIN) {
        float a1 = 0.f, a2 = 0.f;
#pragma unroll
        for (int f = 0; f < FOUT; f++) {
            float w = W[t * FOUT + f];
            a1 += w * a[f];
            a2 += w * a[FOUT + f];
        }
        d_u1[t] = a1;
        d_u2[t] = a2;
    }
}

// ---------------- K2: s1,s2 per row; one warp per row ----------------
__global__ void k_scores(const float* __restrict__ h) {
    __shared__ float su1[FIN], su2[FIN];
    int tid = threadIdx.x;          // 256 threads = 8 warps
    if (tid < FIN) { su1[tid] = d_u1[tid]; su2[tid] = d_u2[tid]; }
    __syncthreads();
    int warp = tid >> 5, lane = tid & 31;
    int row = blockIdx.x * 8 + warp;
    float4 hv = ((const float4*)h)[(size_t)row * (FIN / 4) + lane];
    int c = lane * 4;
    float a1 = hv.x * su1[c] + hv.y * su1[c + 1] + hv.z * su1[c + 2] + hv.w * su1[c + 3];
    float a2 = hv.x * su2[c] + hv.y * su2[c + 1] + hv.z * su2[c + 2] + hv.w * su2[c + 3];
#pragma unroll
    for (int o = 16; o; o >>= 1) {
        a1 += __shfl_xor_sync(0xffffffffu, a1, o);
        a2 += __shfl_xor_sync(0xffffffffu, a2, o);
    }
    if (lane == 0) { d_s1[row] = a1; d_s2[row] = a2; }
}

// gather per-bin payload sums (.y,.z of packed float4), excl-scan 1024 bins.
// totals -> bc[4], bc[5]. Caller syncs after.
__device__ __forceinline__ void binscan_f4(
    const float4* pk, const int* off,
    float* binA, float* binB, float* wsA, float* wsB, volatile float* bc,
    int tid, int lane, int wid)
{
    int s = off[tid], e = off[tid + 1];
    float sa = 0.f, sb = 0.f;
    for (int p = s; p < e; p++) {
        float4 v = pk[p];
        sa += v.y; sb += v.z;
    }
    float ia = sa, ib = sb;
#pragma unroll
    for (int o = 1; o < 32; o <<= 1) {
        float ay = __shfl_up_sync(0xffffffffu, ia, o);
        float by = __shfl_up_sync(0xffffffffu, ib, o);
        if (lane >= o) { ia += ay; ib += by; }
    }
    if (lane == 31) { wsA[wid] = ia; wsB[wid] = ib; }
    __syncthreads();
    if (wid == 0) {
        float aw = wsA[lane], bw = wsB[lane];
        float awi = aw, bwi = bw;
#pragma unroll
        for (int o = 1; o < 32; o <<= 1) {
            float ay = __shfl_up_sync(0xffffffffu, awi, o);
            float by = __shfl_up_sync(0xffffffffu, bwi, o);
            if (lane >= o) { awi += ay; bwi += by; }
        }
        wsA[lane] = awi - aw; wsB[lane] = bwi - bw;
        if (lane == 31) { bc[4] = awi; bc[5] = bwi; }
    }
    __syncthreads();
    binA[tid] = ia - sa + wsA[wid];
    binB[tid] = ib - sb + wsB[wid];
}

// ---------------- K3: per-batch softmax column mass c[j] ----------------
__global__ void __launch_bounds__(1024, 1) k_attn() {
    int b = blockIdx.x;
    int tid = threadIdx.x;          // 1024
    int lane = tid & 31, wid = tid >> 5;

    extern __shared__ __align__(16) char dyn[];
    float4* pk2 = (float4*)dyn;                 // (s2, e^{s2}, e^{.2 s2}, -)
    float4* pk1 = pk2 + N;                      // (s1, g1, g2, -)
    float*  binA = (float*)(pk1 + N);
    float*  binB = binA + NB;
    int*    cnt2 = (int*)(binB + NB);
    int*    cnt1 = cnt2 + NB;
    int*    off2 = cnt1 + NB;
    int*    off1 = off2 + (NB + 1);

    __shared__ float wsA[32], wsB[32];
    __shared__ int   wsI[32], wsJ[32];
    __shared__ float bc[8];   // lo2,hi2,lo1,hi1,totA,totB

    float rs1[2], rs2[2];
    {
        const float* gs1 = d_s1 + b * N;
        const float* gs2 = d_s2 + b * N;
#pragma unroll
        for (int r = 0; r < 2; r++) {
            int i = tid + (r << 10);
            rs1[r] = gs1[i];
            rs2[r] = gs2[i];
        }
    }
    cnt2[tid] = 0;
    cnt1[tid] = 0;

    // min/max of s1, s2 (binA[0..127] as scratch)
    {
        float l1 = fminf(rs1[0], rs1[1]), h1 = fmaxf(rs1[0], rs1[1]);
        float l2 = fminf(rs2[0], rs2[1]), h2 = fmaxf(rs2[0], rs2[1]);
#pragma unroll
        for (int o = 16; o; o >>= 1) {
            l1 = fminf(l1, __shfl_xor_sync(0xffffffffu, l1, o));
            h1 = fmaxf(h1, __shfl_xor_sync(0xffffffffu, h1, o));
            l2 = fminf(l2, __shfl_xor_sync(0xffffffffu, l2, o));
            h2 = fmaxf(h2, __shfl_xor_sync(0xffffffffu, h2, o));
        }
        if (lane == 0) {
            binA[wid] = l1; binA[32 + wid] = h1;
            binA[64 + wid] = l2; binA[96 + wid] = h2;
        }
        __syncthreads();
        if (wid == 0) {
            float a0 = binA[lane], a1m = binA[32 + lane];
            float a2m = binA[64 + lane], a3 = binA[96 + lane];
#pragma unroll
            for (int o = 16; o; o >>= 1) {
                a0  = fminf(a0,  __shfl_xor_sync(0xffffffffu, a0, o));
                a1m = fmaxf(a1m, __shfl_xor_sync(0xffffffffu, a1m, o));
                a2m = fminf(a2m, __shfl_xor_sync(0xffffffffu, a2m, o));
                a3  = fmaxf(a3,  __shfl_xor_sync(0xffffffffu, a3, o));
            }
            if (lane == 0) { bc[0] = a2m; bc[1] = a3; bc[2] = a0; bc[3] = a1m; }
        }
        __syncthreads();
    }

    float lo2 = bc[0], hi2 = bc[1];
    float lo1 = bc[2], hi1 = bc[3];
    float scale2 = (hi2 > lo2) ? ((float)NB / (hi2 - lo2)) : 0.f;
    float scale1 = (hi1 > lo1) ? ((float)NB / (hi1 - lo1)) : 0.f;

    // ===== dual histogram (one int atomic per element per structure) =====
    int bn2[2], bn1[2], rk2[2], rk1[2];
#pragma unroll
    for (int r = 0; r < 2; r++) {
        bn2[r] = binOf(rs2[r], lo2, scale2);
        rk2[r] = atomicAdd(&cnt2[bn2[r]], 1);
        bn1[r] = binOf(rs1[r], lo1, scale1);
        rk1[r] = atomicAdd(&cnt1[bn1[r]], 1);
    }
    __syncthreads();

    // ===== dual exclusive count scan -> off2, off1 =====
    {
        int c2 = cnt2[tid], c1 = cnt1[tid];
        int i2 = c2, i1 = c1;
#pragma unroll
        for (int o = 1; o < 32; o <<= 1) {
            int y2 = __shfl_up_sync(0xffffffffu, i2, o);
            int y1 = __shfl_up_sync(0xffffffffu, i1, o);
            if (lane >= o) { i2 += y2; i1 += y1; }
        }
        if (lane == 31) { wsI[wid] = i2; wsJ[wid] = i1; }
        __syncthreads();
        if (wid == 0) {
            int w2 = wsI[lane], w1 = wsJ[lane];
            int j2 = w2, j1 = w1;
#pragma unroll
            for (int o = 1; o < 32; o <<= 1) {
                int y2 = __shfl_up_sync(0xffffffffu, j2, o);
                int y1 = __shfl_up_sync(0xffffffffu, j1, o);
                if (lane >= o) { j2 += y2; j1 += y1; }
            }
            wsI[lane] = j2 - w2; wsJ[lane] = j1 - w1;
        }
        __syncthreads();
        off2[tid] = i2 - c2 + wsI[wid];
        off1[tid] = i1 - c1 + wsJ[wid];
        if (tid == 0) { off2[NB] = N; off1[NB] = N; }
    }
    __syncthreads();

    // ===== dual scatter: struct2 full payload; struct1 key only =====
    int p1s[2];
#pragma unroll
    for (int r = 0; r < 2; r++) {
        float eA = __expf(rs2[r]);
        float eB = __expf(ALPHA * rs2[r]);
        int p = off2[bn2[r]] + rk2[r];
        pk2[p] = make_float4(rs2[r], eA, eB, 0.f);
        int q = off1[bn1[r]] + rk1[r];
        pk1[q] = make_float4(rs1[r], 0.f, 0.f, 0.f);
        p1s[r] = q;
    }
    __syncthreads();

    // ===== struct2 payload bin sums + scan =====
    binscan_f4(pk2, off2, binA, binB, wsA, wsB, bc, tid, lane, wid);
    __syncthreads();

    // ===== pass-1 queries -> g; write g into struct1 payload slots =====
    {
        float smax = bc[1], tA = bc[4], tB = bc[5];
        float* p1f = (float*)pk1;
#pragma unroll
        for (int r = 0; r < 2; r++) {
            float s1 = rs1[r];
            float t = -s1;
            int qb = binOf(t, lo2, scale2);
            float SA = binA[qb], SB = binB[qb];
            int pe = off2[qb + 1];
            for (int p = off2[qb]; p < pe; p++) {
                float4 v = pk2[p];
                if (v.x <= t) { SA += v.y; SB += v.z; }
            }
            float Apos = tA - SA;               // sum e^{s2} over s2 > -s1
            float m = leaky(s1 + smax);
            float e1 = __expf(s1 - m);
            float e2 = __expf(ALPHA * s1 - m);
            float inv = 1.0f / (e1 * Apos + e2 * SB);
            p1f[4 * p1s[r] + 1] = e1 * inv;     // g1
            p1f[4 * p1s[r] + 2] = e2 * inv;     // g2
        }
    }
    __syncthreads();

    // ===== struct1 payload bin sums + scan (reuses binA/binB) =====
    binscan_f4(pk1, off1, binA, binB, wsA, wsB, bc, tid, lane, wid);
    __syncthreads();

    // ===== pass-2 queries -> column mass c_j =====
    {
        float tG1 = bc[4], tG2 = bc[5];
#pragma unroll
        for (int r = 0; r < 2; r++) {
            int j = tid + (r << 10);
            float s2 = rs2[r];
            float t = -s2;
            int qb = binOf(t, lo1, scale1);
            float SG1 = binA[qb], SG2 = binB[qb];
            int pe = off1[qb + 1];
            for (int p = off1[qb]; p < pe; p++) {
                float4 v = pk1[p];
                if (v.x <= t) { SG1 += v.y; SG2 += v.z; }
            }
            float P = tG1 - SG1;                // sum g1 over s1 > -s2
            float c = __expf(s2) * P + __expf(ALPHA * s2) * SG2;
            d_c[b * N + j] = c;
        }
    }
}

// ---------------- K4: v[b,:] = sum_j c[b,j] * h[b,j,:] ----------------
// 512 blocks, 8 warps x 4 rows each, float4 loads, smem reduce, 128 atomics/block
__global__ void k_wsum(const float* __restrict__ h) {
    __shared__ float red[8 * FIN];
    int b = blockIdx.x >> 6;              // grid = B*64
    int chunk = blockIdx.x & 63;
    int wid = threadIdx.x >> 5, lane = threadIdx.x & 31;   // 256 threads
    const float4* h4 = (const float4*)h;
    const float* cb = d_c + b * N;
    size_t base = (size_t)b * N * (FIN / 4);
    int j0 = chunk * 32 + wid * 4;
    float c0 = cb[j0], c1 = cb[j0 + 1], c2 = cb[j0 + 2], c3 = cb[j0 + 3];
    float4 h0 = h4[base + (size_t)(j0 + 0) * (FIN / 4) + lane];
    float4 h1 = h4[base + (size_t)(j0 + 1) * (FIN / 4) + lane];
    float4 h2 = h4[base + (size_t)(j0 + 2) * (FIN / 4) + lane];
    float4 h3 = h4[base + (size_t)(j0 + 3) * (FIN / 4) + lane];
    float4 acc;
    acc.x = c0 * h0.x + c1 * h1.x + c2 * h2.x + c3 * h3.x;
    acc.y = c0 * h0.y + c1 * h1.y + c2 * h2.y + c3 * h3.y;
    acc.z = c0 * h0.z + c1 * h1.z + c2 * h2.z + c3 * h3.z;
    acc.w = c0 * h0.w + c1 * h1.w + c2 * h2.w + c3 * h3.w;
    ((float4*)red)[wid * 32 + lane] = acc;
    __syncthreads();
    if (threadIdx.x < FIN) {
        int k = threadIdx.x;
        float s = 0.f;
#pragma unroll
        for (int w = 0; w < 8; w++) s += red[w * FIN + k];
        atomicAdd(&d_v[b * FIN + k], s);
    }
}

// ---------------- K5: out[b,f] = (1/N) * v[b,:] . W[:,f] ----------------
// one block per batch, 512 threads = 64 f-lanes x 8 k-groups of 16; W coalesced
__global__ void k_out(const float* __restrict__ W, float* __restrict__ out) {
    __shared__ float sv[FIN];
    __shared__ float part[8][FOUT];
    int b = blockIdx.x;
    int tid = threadIdx.x;                // 512
    int f = tid & 63, kg = tid >> 6;      // kg in 0..7
    if (tid < FIN) sv[tid] = d_v[b * FIN + tid];
    __syncthreads();
    float acc = 0.f;
#pragma unroll
    for (int q = 0; q < 16; q++) {
        int k = kg * 16 + q;
        acc = fmaf(sv[k], W[k * FOUT + f], acc);
    }
    part[kg][f] = acc;
    __syncthreads();
    if (tid < FOUT) {
        float s = 0.f;
#pragma unroll
        for (int g = 0; g < 8; g++) s += part[g][tid];
        out[b * FOUT + tid] = s * (1.0f / (float)N);
    }
}

extern "C" void kernel_launch(void* const* d_in, const int* in_sizes, int n_in,
                              void* d_out, int out_size) {
    (void)in_sizes; (void)n_in; (void)out_size;
    const float* h = (const float*)d_in[0];
    const float* W = (const float*)d_in[1];
    const float* a = (const float*)d_in[2];
    float* out = (float*)d_out;

    cudaFuncSetAttribute(k_attn, cudaFuncAttributeMaxDynamicSharedMemorySize, SMEM_ATTN);

    k_prep<<<1, 1024>>>(W, a);
    k_scores<<<(B * N) / 8, 256>>>(h);
    k_attn<<<B, 1024, SMEM_ATTN>>>();
    k_wsum<<<B * 64, 256>>>(h);
    k_out<<<B, 512>>>(W, out);
}

// round 13
// speedup vs baseline: 1.1618x; 1.1618x over previous
#include <cuda_runtime.h>
#include <cuda_bf16.h>
#include <math.h>

// GAT layer, fully collapsed:
//   s1 = h @ (W a1), s2 = h @ (W a2)
//   m_i = leaky(s1_i + max_j s2_j)
//   Z_i = e^{s1_i-m_i} * SUM_{s2_j > -s1_i} e^{s2_j} + e^{.2 s1_i-m_i} * SUM_{s2_j <= -s1_i} e^{.2 s2_j}
//   c_j = e^{s2_j} * SUM_{s1_i > -s2_j} g1_i + e^{.2 s2_j} * SUM_{s1_i <= -s2_j} g2_i
//   out[b] = (1/N) * (c^T h) @ W
// Threshold sums via 1024-bin bucket structure (R11 version — kept frozen):
// histogram atomic returns the in-bin rank, scatter is atomic-free, bin sums
// gathered + shuffle-scanned. Branch selection is exact fp compare.
// This round: k_prep folded into k_scores (u=W·a per block, 128 blocks) and
// d_v zeroing moved into k_attn -> 4 launches.

#define B 8
#define N 2048
#define FIN 128
#define FOUT 64
#define ALPHA 0.2f
#define NB 1024

__device__ float d_s1[B * N];
__device__ float d_s2[B * N];
__device__ float d_c[B * N];
__device__ float d_v[B * FIN];

__device__ __forceinline__ float leaky(float x) { return x >= 0.f ? x : ALPHA * x; }

__device__ __forceinline__ int binOf(float x, float lo, float scale) {
    float f = (x - lo) * scale;
    f = fminf(fmaxf(f, 0.f), (float)(NB - 1));
    return (int)f;
}

// ---------------- K1: s1,s2 per row; u = W·a computed per block ----------------
// grid = 128 blocks x 256 threads; each block: u (from 32KB W, L2-hot) + 128 rows
__global__ void k_scores(const float* __restrict__ h, const float* __restrict__ W,
                         const float* __restrict__ a) {
    __shared__ float su1[FIN], su2[FIN];
    int tid = threadIdx.x;          // 256 threads = 8 warps
    {   // threads 0..127: u1[t] = W[t,:].a1 ; threads 128..255: u2[t] = W[t,:].a2
        int t = tid & 127;
        const float4* W4 = (const float4*)W;
        const float* av = a + ((tid < 128) ? 0 : FOUT);
        float acc = 0.f;
#pragma unroll
        for (int q = 0; q < 16; q++) {
            float4 w = W4[t * 16 + q];
            acc += w.x * av[q * 4] + w.y * av[q * 4 + 1] +
                   w.z * av[q * 4 + 2] + w.w * av[q * 4 + 3];
        }
        if (tid < 128) su1[t] = acc; else su2[t] = acc;
    }
    __syncthreads();

    int warp = tid >> 5, lane = tid & 31;
    int c = lane * 4;
    float u1a = su1[c], u1b = su1[c + 1], u1c = su1[c + 2], u1d = su1[c + 3];
    float u2a = su2[c], u2b = su2[c + 1], u2c = su2[c + 2], u2d = su2[c + 3];

    const float4* h4 = (const float4*)h;
    int row0 = blockIdx.x * 128 + warp * 16;       // 16 rows per warp
#pragma unroll
    for (int g = 0; g < 4; g++) {                  // 4 rows in flight at a time
        float4 hv[4];
#pragma unroll
        for (int r = 0; r < 4; r++)
            hv[r] = h4[(size_t)(row0 + g * 4 + r) * (FIN / 4) + lane];
#pragma unroll
        for (int r = 0; r < 4; r++) {
            float a1 = hv[r].x * u1a + hv[r].y * u1b + hv[r].z * u1c + hv[r].w * u1d;
            float a2 = hv[r].x * u2a + hv[r].y * u2b + hv[r].z * u2c + hv[r].w * u2d;
#pragma unroll
            for (int o = 16; o; o >>= 1) {
                a1 += __shfl_xor_sync(0xffffffffu, a1, o);
                a2 += __shfl_xor_sync(0xffffffffu, a2, o);
            }
            if (lane == 0) {
                d_s1[row0 + g * 4 + r] = a1;
                d_s2[row0 + g * 4 + r] = a2;
            }
        }
    }
}

// Build the bucket structure for keys (k0,k1) with payloads (a,b) per thread.
// (R11 version — unchanged)
__device__ __forceinline__ void build_struct(
    float k0, float k1, float a0, float a1v, float b0, float b1v,
    float lo, float scale,
    float* val, float* pA, float* pB, int* cnt, int* off,
    float* binA, float* binB,
    float* wsA, float* wsB, int* wsI,
    float* totA, float* totB,
    int tid, int lane, int wid)
{
    cnt[tid] = 0;
    __syncthreads();
    int bn0 = binOf(k0, lo, scale);
    int bn1 = binOf(k1, lo, scale);
    int rk0 = atomicAdd(&cnt[bn0], 1);
    int rk1 = atomicAdd(&cnt[bn1], 1);
    __syncthreads();

    // exclusive scan of counts -> off
    {
        int c = cnt[tid];
        int ci = c;
#pragma unroll
        for (int o = 1; o < 32; o <<= 1) {
            int cy = __shfl_up_sync(0xffffffffu, ci, o);
            if (lane >= o) ci += cy;
        }
        if (lane == 31) wsI[wid] = ci;
        __syncthreads();
        if (wid == 0) {
            int cw = wsI[lane];
            int cwi = cw;
#pragma unroll
            for (int o = 1; o < 32; o <<= 1) {
                int cy = __shfl_up_sync(0xffffffffu, cwi, o);
                if (lane >= o) cwi += cy;
            }
            wsI[lane] = cwi - cw;
        }
        __syncthreads();
        off[tid] = ci - c + wsI[wid];
        if (tid == 0) off[NB] = N;
    }
    __syncthreads();

    // scatter (atomic-free: rank from histogram)
    {
        int p0 = off[bn0] + rk0;
        int p1 = off[bn1] + rk1;
        val[p0] = k0;  pA[p0] = a0;  pB[p0] = b0;
        val[p1] = k1;  pA[p1] = a1v; pB[p1] = b1v;
    }
    __syncthreads();

    // gather per-bin sums, then combined exclusive scan over 1024 bins
    {
        int s = off[tid], e = off[tid + 1];
        float sa = 0.f, sb = 0.f;
        for (int p = s; p < e; p++) { sa += pA[p]; sb += pB[p]; }
        float ia = sa, ib = sb;
#pragma unroll
        for (int o = 1; o < 32; o <<= 1) {
            float ay = __shfl_up_sync(0xffffffffu, ia, o);
            float by = __shfl_up_sync(0xffffffffu, ib, o);
            if (lane >= o) { ia += ay; ib += by; }
        }
        if (lane == 31) { wsA[wid] = ia; wsB[wid] = ib; }
        __syncthreads();
        if (wid == 0) {
            float aw = wsA[lane], bw = wsB[lane];
            float awi = aw, bwi = bw;
#pragma unroll
            for (int o = 1; o < 32; o <<= 1) {
                float ay = __shfl_up_sync(0xffffffffu, awi, o);
                float by = __shfl_up_sync(0xffffffffu, bwi, o);
                if (lane >= o) { awi += ay; bwi += by; }
            }
            wsA[lane] = awi - aw; wsB[lane] = bwi - bw;
            if (lane == 31) { *totA = awi; *totB = bwi; }
        }
        __syncthreads();
        binA[tid] = ia - sa + wsA[wid];
        binB[tid] = ib - sb + wsB[wid];
    }
    __syncthreads();
}

// ---------------- K2: per-batch softmax column mass c[j] ----------------
__global__ void __launch_bounds__(1024, 1) k_attn() {
    int b = blockIdx.x;
    int tid = threadIdx.x;          // 1024
    int lane = tid & 31, wid = tid >> 5;

    __shared__ float val[N], pA[N], pB[N];
    __shared__ float binA[NB], binB[NB];
    __shared__ int   cnt[NB];
    __shared__ int   off[NB + 1];
    __shared__ float wsA[32], wsB[32];
    __shared__ int   wsI[32];
    __shared__ float bc[8];   // lo2,hi2,lo1,hi1,totA,totB

    float rs1[2], rs2[2];
    {
        const float* gs1 = d_s1 + b * N;
        const float* gs2 = d_s2 + b * N;
#pragma unroll
        for (int r = 0; r < 2; r++) {
            int i = tid + (r << 10);
            rs1[r] = gs1[i];
            rs2[r] = gs2[i];
        }
    }
    if (tid < FIN) d_v[b * FIN + tid] = 0.f;   // zero accumulator for k_wsum

    // min/max of s1, s2
    {
        float l1 = fminf(rs1[0], rs1[1]), h1 = fmaxf(rs1[0], rs1[1]);
        float l2 = fminf(rs2[0], rs2[1]), h2 = fmaxf(rs2[0], rs2[1]);
#pragma unroll
        for (int o = 16; o; o >>= 1) {
            l1 = fminf(l1, __shfl_xor_sync(0xffffffffu, l1, o));
            h1 = fmaxf(h1, __shfl_xor_sync(0xffffffffu, h1, o));
            l2 = fminf(l2, __shfl_xor_sync(0xffffffffu, l2, o));
            h2 = fmaxf(h2, __shfl_xor_sync(0xffffffffu, h2, o));
        }
        if (lane == 0) {
            val[wid] = l1; val[32 + wid] = h1; val[64 + wid] = l2; val[96 + wid] = h2;
        }
        __syncthreads();
        if (wid == 0) {
            float a0 = val[lane], a1m = val[32 + lane];
            float a2m = val[64 + lane], a3 = val[96 + lane];
#pragma unroll
            for (int o = 16; o; o >>= 1) {
                a0  = fminf(a0,  __shfl_xor_sync(0xffffffffu, a0, o));
                a1m = fmaxf(a1m, __shfl_xor_sync(0xffffffffu, a1m, o));
                a2m = fminf(a2m, __shfl_xor_sync(0xffffffffu, a2m, o));
                a3  = fmaxf(a3,  __shfl_xor_sync(0xffffffffu, a3, o));
            }
            if (lane == 0) { bc[0] = a2m; bc[1] = a3; bc[2] = a0; bc[3] = a1m; }
        }
        __syncthreads();
    }

    // ===== PASS 1: key = s2, payload (e^{s2}, e^{.2 s2}) =====
    float lo2 = bc[0], hi2 = bc[1];
    float scale2 = (hi2 > lo2) ? ((float)NB / (hi2 - lo2)) : 0.f;

    float eA0 = __expf(rs2[0]),          eA1 = __expf(rs2[1]);
    float eB0 = __expf(ALPHA * rs2[0]),  eB1 = __expf(ALPHA * rs2[1]);

    build_struct(rs2[0], rs2[1], eA0, eA1, eB0, eB1, lo2, scale2,
                 val, pA, pB, cnt, off, binA, binB, wsA, wsB, wsI,
                 &bc[4], &bc[5], tid, lane, wid);

    float g1[2], g2[2];
    {
        float smax = bc[1], tA = bc[4], tB = bc[5];
#pragma unroll
        for (int r = 0; r < 2; r++) {
            float s1 = rs1[r];
            float t = -s1;
            int qb = binOf(t, lo2, scale2);
            float SA = binA[qb], SB = binB[qb];
            int pe = off[qb + 1];
            for (int p = off[qb]; p < pe; p++) {
                if (val[p] <= t) { SA += pA[p]; SB += pB[p]; }
            }
            float Apos = tA - SA;               // sum e^{s2} over s2 > -s1
            float m = leaky(s1 + smax);
            float e1 = __expf(s1 - m);
            float e2 = __expf(ALPHA * s1 - m);
            float inv = 1.0f / (e1 * Apos + e2 * SB);
            g1[r] = e1 * inv;
            g2[r] = e2 * inv;
        }
    }
    __syncthreads();   // done reading pass-1 structure

    // ===== PASS 2: key = s1, payload (g1, g2) =====
    float lo1 = bc[2], hi1 = bc[3];
    float scale1 = (hi1 > lo1) ? ((float)NB / (hi1 - lo1)) : 0.f;

    build_struct(rs1[0], rs1[1], g1[0], g1[1], g2[0], g2[1], lo1, scale1,
                 val, pA, pB, cnt, off, binA, binB, wsA, wsB, wsI,
                 &bc[4], &bc[5], tid, lane, wid);

    {
        float tG1 = bc[4], tG2 = bc[5];
#pragma unroll
        for (int r = 0; r < 2; r++) {
            int j = tid + (r << 10);
            float s2 = rs2[r];
            float t = -s2;
            int qb = binOf(t, lo1, scale1);
            float SG1 = binA[qb], SG2 = binB[qb];
            int pe = off[qb + 1];
            for (int p = off[qb]; p < pe; p++) {
                if (val[p] <= t) { SG1 += pA[p]; SG2 += pB[p]; }
            }
            float P = tG1 - SG1;                // sum g1 over s1 > -s2
            float c = __expf(s2) * P + __expf(ALPHA * s2) * SG2;
            d_c[b * N + j] = c;
        }
    }
}

// ---------------- K3: v[b,:] = sum_j c[b,j] * h[b,j,:] ----------------
// 512 blocks, 8 warps x 4 rows each, float4 loads, smem reduce, 128 atomics/block
__global__ void k_wsum(const float* __restrict__ h) {
    __shared__ float red[8 * FIN];
    int b = blockIdx.x >> 6;              // grid = B*64
    int chunk = blockIdx.x & 63;
    int wid = threadIdx.x >> 5, lane = threadIdx.x & 31;   // 256 threads
    const float4* h4 = (const float4*)h;
    const float* cb = d_c + b * N;
    size_t base = (size_t)b * N * (FIN / 4);
    int j0 = chunk * 32 + wid * 4;
    float c0 = cb[j0], c1 = cb[j0 + 1], c2 = cb[j0 + 2], c3 = cb[j0 + 3];
    float4 h0 = h4[base + (size_t)(j0 + 0) * (FIN / 4) + lane];
    float4 h1 = h4[base + (size_t)(j0 + 1) * (FIN / 4) + lane];
    float4 h2 = h4[base + (size_t)(j0 + 2) * (FIN / 4) + lane];
    float4 h3 = h4[base + (size_t)(j0 + 3) * (FIN / 4) + lane];
    float4 acc;
    acc.x = c0 * h0.x + c1 * h1.x + c2 * h2.x + c3 * h3.x;
    acc.y = c0 * h0.y + c1 * h1.y + c2 * h2.y + c3 * h3.y;
    acc.z = c0 * h0.z + c1 * h1.z + c2 * h2.z + c3 * h3.z;
    acc.w = c0 * h0.w + c1 * h1.w + c2 * h2.w + c3 * h3.w;
    ((float4*)red)[wid * 32 + lane] = acc;
    __syncthreads();
    if (threadIdx.x < FIN) {
        int k = threadIdx.x;
        float s = 0.f;
#pragma unroll
        for (int w = 0; w < 8; w++) s += red[w * FIN + k];
        atomicAdd(&d_v[b * FIN + k], s);
    }
}

// ---------------- K4: out[b,f] = (1/N) * v[b,:] . W[:,f] ----------------
// one block per batch, 512 threads = 64 f-lanes x 8 k-groups of 16; W coalesced
__global__ void k_out(const float* __restrict__ W, float* __restrict__ out) {
    __shared__ float sv[FIN];
    __shared__ float part[8][FOUT];
    int b = blockIdx.x;
    int tid = threadIdx.x;                // 512
    int f = tid & 63, kg = tid >> 6;      // kg in 0..7
    if (tid < FIN) sv[tid] = d_v[b * FIN + tid];
    __syncthreads();
    float acc = 0.f;
#pragma unroll
    for (int q = 0; q < 16; q++) {
        int k = kg * 16 + q;
        acc = fmaf(sv[k], W[k * FOUT + f], acc);
    }
    part[kg][f] = acc;
    __syncthreads();
    if (tid < FOUT) {
        float s = 0.f;
#pragma unroll
        for (int g = 0; g < 8; g++) s += part[g][tid];
        out[b * FOUT + tid] = s * (1.0f / (float)N);
    }
}

extern "C" void kernel_launch(void* const* d_in, const int* in_sizes, int n_in,
                              void* d_out, int out_size) {
    (void)in_sizes; (void)n_in; (void)out_size;
    const float* h = (const float*)d_in[0];
    const float* W = (const float*)d_in[1];
    const float* a = (const float*)d_in[2];
    float* out = (float*)d_out;

    k_scores<<<128, 256>>>(h, W, a);
    k_attn<<<B, 1024>>>();
    k_wsum<<<B * 64, 256>>>(h);
    k_out<<<B, 512>>>(W, out);
}

// round 14
// speedup vs baseline: 1.1737x; 1.0102x over previous
#include <cuda_runtime.h>
#include <cuda_bf16.h>
#include <math.h>

// GAT layer, fully collapsed:
//   s1 = h @ (W a1), s2 = h @ (W a2)
//   m_i = leaky(s1_i + max_j s2_j)
//   Z_i = e^{s1_i-m_i} * SUM_{s2_j > -s1_i} e^{s2_j} + e^{.2 s1_i-m_i} * SUM_{s2_j <= -s1_i} e^{.2 s2_j}
//   c_j = e^{s2_j} * SUM_{s1_i > -s2_j} g1_i + e^{.2 s2_j} * SUM_{s1_i <= -s2_j} g2_i
//   out[b] = (1/N) * (c^T h) @ W
// Threshold sums via 1024-bin bucket structures. This round: dual-skeleton
// build (both histograms / one fused count-scan / both scatters share
// barriers) with SCALAR element arrays (no float4 packing — that was the R12
// regression). Branch selection is exact fp compare.

#define B 8
#define N 2048
#define FIN 128
#define FOUT 64
#define ALPHA 0.2f
#define NB 1024

// dynamic smem: val2,pA2,pB2,val1,pA1,pB1 [N] each; binA,binB [NB];
//               cnt2,cnt1 [NB] int; off2,off1 [NB+1] int
#define SMEM_ATTN (6 * N * 4 + 2 * NB * 4 + 2 * NB * 4 + 2 * (NB + 1) * 4)

__device__ float d_s1[B * N];
__device__ float d_s2[B * N];
__device__ float d_c[B * N];
__device__ float d_v[B * FIN];

__device__ __forceinline__ float leaky(float x) { return x >= 0.f ? x : ALPHA * x; }

__device__ __forceinline__ int binOf(float x, float lo, float scale) {
    float f = (x - lo) * scale;
    f = fminf(fmaxf(f, 0.f), (float)(NB - 1));
    return (int)f;
}

// ---------------- K1: s1,s2 per row; u = W·a computed per block ----------------
// grid = 128 blocks x 256 threads (unchanged from R13)
__global__ void k_scores(const float* __restrict__ h, const float* __restrict__ W,
                         const float* __restrict__ a) {
    __shared__ float su1[FIN], su2[FIN];
    int tid = threadIdx.x;          // 256 threads = 8 warps
    {
        int t = tid & 127;
        const float4* W4 = (const float4*)W;
        const float* av = a + ((tid < 128) ? 0 : FOUT);
        float acc = 0.f;
#pragma unroll
        for (int q = 0; q < 16; q++) {
            float4 w = W4[t * 16 + q];
            acc += w.x * av[q * 4] + w.y * av[q * 4 + 1] +
                   w.z * av[q * 4 + 2] + w.w * av[q * 4 + 3];
        }
        if (tid < 128) su1[t] = acc; else su2[t] = acc;
    }
    __syncthreads();

    int warp = tid >> 5, lane = tid & 31;
    int c = lane * 4;
    float u1a = su1[c], u1b = su1[c + 1], u1c = su1[c + 2], u1d = su1[c + 3];
    float u2a = su2[c], u2b = su2[c + 1], u2c = su2[c + 2], u2d = su2[c + 3];

    const float4* h4 = (const float4*)h;
    int row0 = blockIdx.x * 128 + warp * 16;       // 16 rows per warp
#pragma unroll
    for (int g = 0; g < 4; g++) {
        float4 hv[4];
#pragma unroll
        for (int r = 0; r < 4; r++)
            hv[r] = h4[(size_t)(row0 + g * 4 + r) * (FIN / 4) + lane];
#pragma unroll
        for (int r = 0; r < 4; r++) {
            float a1 = hv[r].x * u1a + hv[r].y * u1b + hv[r].z * u1c + hv[r].w * u1d;
            float a2 = hv[r].x * u2a + hv[r].y * u2b + hv[r].z * u2c + hv[r].w * u2d;
#pragma unroll
            for (int o = 16; o; o >>= 1) {
                a1 += __shfl_xor_sync(0xffffffffu, a1, o);
                a2 += __shfl_xor_sync(0xffffffffu, a2, o);
            }
            if (lane == 0) {
                d_s1[row0 + g * 4 + r] = a1;
                d_s2[row0 + g * 4 + r] = a2;
            }
        }
    }
}

// gather per-bin payload sums from scattered scalar arrays, excl-scan 1024 bins.
// totals -> bc[4], bc[5]. Caller syncs after.
__device__ __forceinline__ void binscan(
    const float* pA, const float* pB, const int* off,
    float* binA, float* binB, float* wsA, float* wsB, volatile float* bc,
    int tid, int lane, int wid)
{
    int s = off[tid], e = off[tid + 1];
    float sa = 0.f, sb = 0.f;
    for (int p = s; p < e; p++) { sa += pA[p]; sb += pB[p]; }
    float ia = sa, ib = sb;
#pragma unroll
    for (int o = 1; o < 32; o <<= 1) {
        float ay = __shfl_up_sync(0xffffffffu, ia, o);
        float by = __shfl_up_sync(0xffffffffu, ib, o);
        if (lane >= o) { ia += ay; ib += by; }
    }
    if (lane == 31) { wsA[wid] = ia; wsB[wid] = ib; }
    __syncthreads();
    if (wid == 0) {
        float aw = wsA[lane], bw = wsB[lane];
        float awi = aw, bwi = bw;
#pragma unroll
        for (int o = 1; o < 32; o <<= 1) {
            float ay = __shfl_up_sync(0xffffffffu, awi, o);
            float by = __shfl_up_sync(0xffffffffu, bwi, o);
            if (lane >= o) { awi += ay; bwi += by; }
        }
        wsA[lane] = awi - aw; wsB[lane] = bwi - bw;
        if (lane == 31) { bc[4] = awi; bc[5] = bwi; }
    }
    __syncthreads();
    binA[tid] = ia - sa + wsA[wid];
    binB[tid] = ib - sb + wsB[wid];
}

// ---------------- K2: per-batch softmax column mass c[j] ----------------
__global__ void __launch_bounds__(1024, 1) k_attn() {
    int b = blockIdx.x;
    int tid = threadIdx.x;          // 1024
    int lane = tid & 31, wid = tid >> 5;

    extern __shared__ __align__(16) char dyn[];
    float* val2 = (float*)dyn;
    float* pA2  = val2 + N;
    float* pB2  = pA2 + N;
    float* val1 = pB2 + N;
    float* pA1  = val1 + N;
    float* pB1  = pA1 + N;
    float* binA = pB1 + N;
    float* binB = binA + NB;
    int*   cnt2 = (int*)(binB + NB);
    int*   cnt1 = cnt2 + NB;
    int*   off2 = cnt1 + NB;
    int*   off1 = off2 + (NB + 1);

    __shared__ float wsA[32], wsB[32];
    __shared__ int   wsI[32], wsJ[32];
    __shared__ float bc[8];   // lo2,hi2,lo1,hi1,totA,totB

    float rs1[2], rs2[2];
    {
        const float* gs1 = d_s1 + b * N;
        const float* gs2 = d_s2 + b * N;
#pragma unroll
        for (int r = 0; r < 2; r++) {
            int i = tid + (r << 10);
            rs1[r] = gs1[i];
            rs2[r] = gs2[i];
        }
    }
    if (tid < FIN) d_v[b * FIN + tid] = 0.f;   // zero accumulator for k_wsum
    cnt2[tid] = 0;
    cnt1[tid] = 0;

    // min/max of s1, s2 (val2[0..127] as scratch; covered by the same syncs)
    {
        float l1 = fminf(rs1[0], rs1[1]), h1 = fmaxf(rs1[0], rs1[1]);
        float l2 = fminf(rs2[0], rs2[1]), h2 = fmaxf(rs2[0], rs2[1]);
#pragma unroll
        for (int o = 16; o; o >>= 1) {
            l1 = fminf(l1, __shfl_xor_sync(0xffffffffu, l1, o));
            h1 = fmaxf(h1, __shfl_xor_sync(0xffffffffu, h1, o));
            l2 = fminf(l2, __shfl_xor_sync(0xffffffffu, l2, o));
            h2 = fmaxf(h2, __shfl_xor_sync(0xffffffffu, h2, o));
        }
        if (lane == 0) {
            val2[wid] = l1; val2[32 + wid] = h1;
            val2[64 + wid] = l2; val2[96 + wid] = h2;
        }
        __syncthreads();
        if (wid == 0) {
            float a0 = val2[lane], a1m = val2[32 + lane];
            float a2m = val2[64 + lane], a3 = val2[96 + lane];
#pragma unroll
            for (int o = 16; o; o >>= 1) {
                a0  = fminf(a0,  __shfl_xor_sync(0xffffffffu, a0, o));
                a1m = fmaxf(a1m, __shfl_xor_sync(0xffffffffu, a1m, o));
                a2m = fminf(a2m, __shfl_xor_sync(0xffffffffu, a2m, o));
                a3  = fmaxf(a3,  __shfl_xor_sync(0xffffffffu, a3, o));
            }
            if (lane == 0) { bc[0] = a2m; bc[1] = a3; bc[2] = a0; bc[3] = a1m; }
        }
        __syncthreads();
    }

    float lo2 = bc[0], hi2 = bc[1];
    float lo1 = bc[2], hi1 = bc[3];
    float scale2 = (hi2 > lo2) ? ((float)NB / (hi2 - lo2)) : 0.f;
    float scale1 = (hi1 > lo1) ? ((float)NB / (hi1 - lo1)) : 0.f;

    // ===== dual histogram (one int atomic per element per structure) =====
    int bn2[2], bn1[2], rk2[2], rk1[2];
#pragma unroll
    for (int r = 0; r < 2; r++) {
        bn2[r] = binOf(rs2[r], lo2, scale2);
        rk2[r] = atomicAdd(&cnt2[bn2[r]], 1);
        bn1[r] = binOf(rs1[r], lo1, scale1);
        rk1[r] = atomicAdd(&cnt1[bn1[r]], 1);
    }
    __syncthreads();

    // ===== fused dual exclusive count scan -> off2, off1 =====
    {
        int c2 = cnt2[tid], c1 = cnt1[tid];
        int i2 = c2, i1 = c1;
#pragma unroll
        for (int o = 1; o < 32; o <<= 1) {
            int y2 = __shfl_up_sync(0xffffffffu, i2, o);
            int y1 = __shfl_up_sync(0xffffffffu, i1, o);
            if (lane >= o) { i2 += y2; i1 += y1; }
        }
        if (lane == 31) { wsI[wid] = i2; wsJ[wid] = i1; }
        __syncthreads();
        if (wid == 0) {
            int w2 = wsI[lane], w1 = wsJ[lane];
            int j2 = w2, j1 = w1;
#pragma unroll
            for (int o = 1; o < 32; o <<= 1) {
                int y2 = __shfl_up_sync(0xffffffffu, j2, o);
                int y1 = __shfl_up_sync(0xffffffffu, j1, o);
                if (lane >= o) { j2 += y2; j1 += y1; }
            }
            wsI[lane] = j2 - w2; wsJ[lane] = j1 - w1;
        }
        __syncthreads();
        off2[tid] = i2 - c2 + wsI[wid];
        off1[tid] = i1 - c1 + wsJ[wid];
        if (tid == 0) { off2[NB] = N; off1[NB] = N; }
    }
    __syncthreads();

    // ===== dual scatter: struct2 key+payload; struct1 key only =====
    int p1s[2];
#pragma unroll
    for (int r = 0; r < 2; r++) {
        int p = off2[bn2[r]] + rk2[r];
        val2[p] = rs2[r];
        pA2[p] = __expf(rs2[r]);
        pB2[p] = __expf(ALPHA * rs2[r]);
        int q = off1[bn1[r]] + rk1[r];
        val1[q] = rs1[r];
        p1s[r] = q;
    }
    __syncthreads();

    // ===== struct2 payload bin sums + scan =====
    binscan(pA2, pB2, off2, binA, binB, wsA, wsB, bc, tid, lane, wid);
    __syncthreads();

    // ===== pass-1 queries -> g; write into struct1 payload slots =====
    {
        float smax = bc[1], tA = bc[4], tB = bc[5];
#pragma unroll
        for (int r = 0; r < 2; r++) {
            float s1 = rs1[r];
            float t = -s1;
            int qb = binOf(t, lo2, scale2);
            float SA = binA[qb], SB = binB[qb];
            int pe = off2[qb + 1];
            for (int p = off2[qb]; p < pe; p++) {
                if (val2[p] <= t) { SA += pA2[p]; SB += pB2[p]; }
            }
            float Apos = tA - SA;               // sum e^{s2} over s2 > -s1
            float m = leaky(s1 + smax);
            float e1 = __expf(s1 - m);
            float e2 = __expf(ALPHA * s1 - m);
            float inv = 1.0f / (e1 * Apos + e2 * SB);
            pA1[p1s[r]] = e1 * inv;             // g1
            pB1[p1s[r]] = e2 * inv;             // g2
        }
    }
    __syncthreads();

    // ===== struct1 payload bin sums + scan (reuses binA/binB) =====
    binscan(pA1, pB1, off1, binA, binB, wsA, wsB, bc, tid, lane, wid);
    __syncthreads();

    // ===== pass-2 queries -> column mass c_j =====
    {
        float tG1 = bc[4], tG2 = bc[5];
#pragma unroll
        for (int r = 0; r < 2; r++) {
            int j = tid + (r << 10);
            float s2 = rs2[r];
            float t = -s2;
            int qb = binOf(t, lo1, scale1);
            float SG1 = binA[qb], SG2 = binB[qb];
            int pe = off1[qb + 1];
            for (int p = off1[qb]; p < pe; p++) {
                if (val1[p] <= t) { SG1 += pA1[p]; SG2 += pB1[p]; }
            }
            float P = tG1 - SG1;                // sum g1 over s1 > -s2
            float c = __expf(s2) * P + __expf(ALPHA * s2) * SG2;
            d_c[b * N + j] = c;
        }
    }
}

// ---------------- K3: v[b,:] = sum_j c[b,j] * h[b,j,:] (unchanged R13) -------
__global__ void k_wsum(const float* __restrict__ h) {
    __shared__ float red[8 * FIN];
    int b = blockIdx.x >> 6;              // grid = B*64
    int chunk = blockIdx.x & 63;
    int wid = threadIdx.x >> 5, lane = threadIdx.x & 31;   // 256 threads
    const float4* h4 = (const float4*)h;
    const float* cb = d_c + b * N;
    size_t base = (size_t)b * N * (FIN / 4);
    int j0 = chunk * 32 + wid * 4;
    float c0 = cb[j0], c1 = cb[j0 + 1], c2 = cb[j0 + 2], c3 = cb[j0 + 3];
    float4 h0 = h4[base + (size_t)(j0 + 0) * (FIN / 4) + lane];
    float4 h1 = h4[base + (size_t)(j0 + 1) * (FIN / 4) + lane];
    float4 h2 = h4[base + (size_t)(j0 + 2) * (FIN / 4) + lane];
    float4 h3 = h4[base + (size_t)(j0 + 3) * (FIN / 4) + lane];
    float4 acc;
    acc.x = c0 * h0.x + c1 * h1.x + c2 * h2.x + c3 * h3.x;
    acc.y = c0 * h0.y + c1 * h1.y + c2 * h2.y + c3 * h3.y;
    acc.z = c0 * h0.z + c1 * h1.z + c2 * h2.z + c3 * h3.z;
    acc.w = c0 * h0.w + c1 * h1.w + c2 * h2.w + c3 * h3.w;
    ((float4*)red)[wid * 32 + lane] = acc;
    __syncthreads();
    if (threadIdx.x < FIN) {
        int k = threadIdx.x;
        float s = 0.f;
#pragma unroll
        for (int w = 0; w < 8; w++) s += red[w * FIN + k];
        atomicAdd(&d_v[b * FIN + k], s);
    }
}

// ---------------- K4: out[b,f] = (1/N) * v[b,:] . W[:,f] (unchanged R13) ----
__global__ void k_out(const float* __restrict__ W, float* __restrict__ out) {
    __shared__ float sv[FIN];
    __shared__ float part[8][FOUT];
    int b = blockIdx.x;
    int tid = threadIdx.x;                // 512
    int f = tid & 63, kg = tid >> 6;      // kg in 0..7
    if (tid < FIN) sv[tid] = d_v[b * FIN + tid];
    __syncthreads();
    float acc = 0.f;
#pragma unroll
    for (int q = 0; q < 16; q++) {
        int k = kg * 16 + q;
        acc = fmaf(sv[k], W[k * FOUT + f], acc);
    }
    part[kg][f] = acc;
    __syncthreads();
    if (tid < FOUT) {
        float s = 0.f;
#pragma unroll
        for (int g = 0; g < 8; g++) s += part[g][tid];
        out[b * FOUT + tid] = s * (1.0f / (float)N);
    }
}

extern "C" void kernel_launch(void* const* d_in, const int* in_sizes, int n_in,
                              void* d_out, int out_size) {
    (void)in_sizes; (void)n_in; (void)out_size;
    const float* h = (const float*)d_in[0];
    const float* W = (const float*)d_in[1];
    const float* a = (const float*)d_in[2];
    float* out = (float*)d_out;

    cudaFuncSetAttribute(k_attn, cudaFuncAttributeMaxDynamicSharedMemorySize, SMEM_ATTN);

    k_scores<<<128, 256>>>(h, W, a);
    k_attn<<<B, 1024, SMEM_ATTN>>>();
    k_wsum<<<B * 64, 256>>>(h);
    k_out<<<B, 512>>>(W, out);
}